// round 7
// baseline (speedup 1.0000x reference)
#include <cuda_runtime.h>

// Embed3D: out[nl, p*40 + 2k + {0,1}] = {sin, cos}(x[nl,1+p] * div_term[k])
// x: (NL,4) fp32, div_term: 20 fp32, out: (NL,120) fp32, NL = 64*8192 = 524288.
//
// R3 winner (float4 .cs stores, contiguous per-slice STG.128) made persistent:
// grid = 148*4 = 592 blocks (one wave), grid-stride loop over 128-row tiles.
// Removes ~6 wave transitions + 3500 block prologues vs the 4096-block launch.

#define THREADS 480
#define ROWS_PER_SLICE 16
#define SLICES 8
#define ROWS_PER_TILE (ROWS_PER_SLICE * SLICES)   // 128
#define GRID_BLOCKS (148 * 4)                     // one full wave on GB300 (152 SMs, use 148*4)

__device__ __forceinline__ void stg_cs_v4(float4* ptr, float4 v) {
    asm volatile("st.global.cs.v4.f32 [%0], {%1, %2, %3, %4};"
                 :: "l"(ptr), "f"(v.x), "f"(v.y), "f"(v.z), "f"(v.w)
                 : "memory");
}

__global__ __launch_bounds__(THREADS)
void embed3d_kernel(const float* __restrict__ x,
                    const float* __restrict__ div_term,
                    float* __restrict__ out,
                    int total_tiles) {
    const int tid = threadIdx.x;
    const int j   = tid % 30;          // float4 slot within a row
    const int r   = tid / 30;          // row within slice (0..15)

    const int p = j / 10;              // pos component 0..2
    const int q = j - p * 10;          // pair group 0..9

    const float d0 = __ldg(&div_term[2 * q]);
    const float d1 = __ldg(&div_term[2 * q + 1]);

    for (int t = blockIdx.x; t < total_tiles; t += GRID_BLOCKS) {
        const int nl_base = t * ROWS_PER_TILE + r;

        // Batch pos loads: 8 independent LDGs in flight.
        float pos[SLICES];
#pragma unroll
        for (int s = 0; s < SLICES; s++) {
            const int nl = nl_base + s * ROWS_PER_SLICE;
            pos[s] = __ldg(&x[nl * 4 + 1 + p]);
        }

#pragma unroll
        for (int s = 0; s < SLICES; s++) {
            const int nl = nl_base + s * ROWS_PER_SLICE;
            float4 v;
            __sincosf(pos[s] * d0, &v.x, &v.y);
            __sincosf(pos[s] * d1, &v.z, &v.w);
            stg_cs_v4(reinterpret_cast<float4*>(out) + nl * 30 + j, v);
        }
    }
}

extern "C" void kernel_launch(void* const* d_in, const int* in_sizes, int n_in,
                              void* d_out, int out_size) {
    const float* x        = (const float*)d_in[0];
    const float* div_term = (const float*)d_in[1];
    float* out            = (float*)d_out;

    const int total_nl = in_sizes[0] / 4;           // 524288, divisible by 128
    const int total_tiles = total_nl / ROWS_PER_TILE;  // 4096

    embed3d_kernel<<<GRID_BLOCKS, THREADS>>>(x, div_term, out, total_tiles);
}

// round 9
// speedup vs baseline: 1.0067x; 1.0067x over previous
#include <cuda_runtime.h>

// Embed3D: out[nl, p*40 + 2k + {0,1}] = {sin, cos}(x[nl,1+p] * div_term[k])
// x: (NL,4) fp32, div_term: 20 fp32, out: (NL,120) fp32, NL = 64*8192 = 524288.
//
// R3 winning recipe (front-batched loads, ILP=8, .cs evict-first, 4 CTA/SM)
// + Blackwell STG.256. Row = 120 floats = 15 float8 slots.
// blockDim=480: j8 = tid%15 (f8 slot), r = tid/15 (row 0..31 per slice),
// 8 slices -> 256 rows/block, grid 2048.
// Global f8 index = nl*15 + j8 = blk*3840 + s*480 + tid  => contiguous;
// each warp's per-slice store burst = 1024B contiguous.

#define THREADS 480
#define ROWS_PER_SLICE 32
#define SLICES 8
#define ROWS_PER_BLOCK (ROWS_PER_SLICE * SLICES)   // 256

__device__ __forceinline__ void stg_cs_v8(float* ptr,
                                          float f0, float f1, float f2, float f3,
                                          float f4, float f5, float f6, float f7) {
    asm volatile(
        "st.global.cs.v8.f32 [%0], {%1, %2, %3, %4, %5, %6, %7, %8};"
        :: "l"(ptr), "f"(f0), "f"(f1), "f"(f2), "f"(f3),
           "f"(f4), "f"(f5), "f"(f6), "f"(f7)
        : "memory");
}

__global__ __launch_bounds__(THREADS, 4)
void embed3d_kernel(const float* __restrict__ x,
                    const float* __restrict__ div_term,
                    float* __restrict__ out,
                    int total_nl) {
    const int tid = threadIdx.x;
    const int j8  = tid % 15;          // float8 slot within a row (0..14)
    const int r   = tid / 15;          // row within slice (0..31)

    const int p  = j8 / 5;             // pos component 0..2
    const int k0 = 4 * (j8 - 5 * p);   // first pair index (0,4,8,12,16)

    const float d0 = __ldg(&div_term[k0]);
    const float d1 = __ldg(&div_term[k0 + 1]);
    const float d2 = __ldg(&div_term[k0 + 2]);
    const float d3 = __ldg(&div_term[k0 + 3]);

    const int nl_base = blockIdx.x * ROWS_PER_BLOCK + r;

    // Front-batch the pos loads: 8 independent LDGs in flight.
    float pos[SLICES];
#pragma unroll
    for (int s = 0; s < SLICES; s++) {
        const int nl = nl_base + s * ROWS_PER_SLICE;
        pos[s] = __ldg(&x[nl * 4 + 1 + p]);
    }

#pragma unroll
    for (int s = 0; s < SLICES; s++) {
        const int nl = nl_base + s * ROWS_PER_SLICE;
        float s0, c0, s1, c1, s2, c2, s3, c3;
        __sincosf(pos[s] * d0, &s0, &c0);
        __sincosf(pos[s] * d1, &s1, &c1);
        __sincosf(pos[s] * d2, &s2, &c2);
        __sincosf(pos[s] * d3, &s3, &c3);
        stg_cs_v8(out + (size_t)(nl * 15 + j8) * 8,
                  s0, c0, s1, c1, s2, c2, s3, c3);
    }
}

extern "C" void kernel_launch(void* const* d_in, const int* in_sizes, int n_in,
                              void* d_out, int out_size) {
    const float* x        = (const float*)d_in[0];
    const float* div_term = (const float*)d_in[1];
    float* out            = (float*)d_out;

    const int total_nl = in_sizes[0] / 4;           // 524288, divisible by 256
    const int grid = total_nl / ROWS_PER_BLOCK;     // 2048

    embed3d_kernel<<<grid, THREADS>>>(x, div_term, out, total_nl);
}

// round 10
// speedup vs baseline: 1.1197x; 1.1123x over previous
#include <cuda_runtime.h>

// Embed3D: out[nl, p*40 + 2k + {0,1}] = {sin, cos}(x[nl,1+p] * div_term[k])
// x: (NL,4) fp32, div_term: 20 fp32, out: (NL,120) fp32, NL = 64*8192 = 524288.
//
// Champion config (R3): blockDim=480 (15 full warps), each thread owns float4
// slot j = tid%30 in rows r, r+16, ..., r+112 (8 slices, 128 rows/block,
// grid 4096). Stores are contiguous STG.128 per slice
// (global float4 index = nl*30 + j) with .cs evict-first (252MB zero-reuse
// write stream). Front-batched pos loads give 8-deep MLP; 8 independent
// sincos/store chains give the ILP. Steady-state: ~6.7 TB/s (~84% of HBM
// spec) on a 97%-write stream — at the practical write ceiling.
// __launch_bounds__(480,4) pins the 4-CTA/SM residency (60 warps).

#define THREADS 480
#define ROWS_PER_SLICE 16
#define SLICES 8
#define ROWS_PER_BLOCK (ROWS_PER_SLICE * SLICES)   // 128

__device__ __forceinline__ void stg_cs_v4(float4* ptr, float4 v) {
    asm volatile("st.global.cs.v4.f32 [%0], {%1, %2, %3, %4};"
                 :: "l"(ptr), "f"(v.x), "f"(v.y), "f"(v.z), "f"(v.w)
                 : "memory");
}

__global__ __launch_bounds__(THREADS, 4)
void embed3d_kernel(const float* __restrict__ x,
                    const float* __restrict__ div_term,
                    float* __restrict__ out,
                    int total_nl) {
    const int tid = threadIdx.x;
    const int j   = tid % 30;          // float4 slot within a row
    const int r   = tid / 30;          // row within slice (0..15)

    const int p = j / 10;              // pos component 0..2
    const int q = j - p * 10;          // pair group 0..9

    const float d0 = __ldg(&div_term[2 * q]);
    const float d1 = __ldg(&div_term[2 * q + 1]);

    const int nl_base = blockIdx.x * ROWS_PER_BLOCK + r;

    // Batch all pos loads up front: 8 independent LDGs in flight.
    float pos[SLICES];
#pragma unroll
    for (int s = 0; s < SLICES; s++) {
        const int nl = nl_base + s * ROWS_PER_SLICE;
        pos[s] = __ldg(&x[nl * 4 + 1 + p]);
    }

#pragma unroll
    for (int s = 0; s < SLICES; s++) {
        const int nl = nl_base + s * ROWS_PER_SLICE;
        float4 v;
        __sincosf(pos[s] * d0, &v.x, &v.y);
        __sincosf(pos[s] * d1, &v.z, &v.w);
        stg_cs_v4(reinterpret_cast<float4*>(out) + nl * 30 + j, v);
    }
}

extern "C" void kernel_launch(void* const* d_in, const int* in_sizes, int n_in,
                              void* d_out, int out_size) {
    const float* x        = (const float*)d_in[0];
    const float* div_term = (const float*)d_in[1];
    float* out            = (float*)d_out;

    const int total_nl = in_sizes[0] / 4;   // 524288, divisible by 128
    const int grid = total_nl / ROWS_PER_BLOCK;   // 4096

    embed3d_kernel<<<grid, THREADS>>>(x, div_term, out, total_nl);
}